// round 1
// baseline (speedup 1.0000x reference)
#include <cuda_runtime.h>
#include <math.h>

#define BATCH 16
#define NA 3
#define NC 80
#define NCH 85            // 5 + NC
#define NT 512            // B*M targets
#define THRESH 0.6f
#define EPSF 1e-7f

// tobj scratch: scale0 16*3*80*80=307200, scale1 76800, scale2 19200 -> 403200 floats
#define TOBJ0 0
#define TOBJ1 307200
#define TOBJ2 384000
#define TOBJ_TOTAL 403200

__device__ float  g_tobj[TOBJ_TOTAL];
__device__ double g_lbox[3];
__device__ double g_lcls[3];
__device__ double g_nb[3];
__device__ double g_lobjsum[3];

__device__ __forceinline__ float bce_logits(float x, float t) {
    // max(x,0) - x*t + log1p(exp(-|x|))
    return fmaxf(x, 0.0f) - x * t + log1pf(expf(-fabsf(x)));
}

__device__ double block_reduce_d(double v, double* sh) {
    int tid = threadIdx.x;
    sh[tid] = v;
    __syncthreads();
    for (int s = blockDim.x >> 1; s > 0; s >>= 1) {
        if (tid < s) sh[tid] += sh[tid + s];
        __syncthreads();
    }
    double r = sh[0];
    __syncthreads();
    return r;
}

__global__ void zero_kernel() {
    int stride = gridDim.x * blockDim.x;
    for (int i = blockIdx.x * blockDim.x + threadIdx.x; i < TOBJ_TOTAL; i += stride)
        g_tobj[i] = 0.0f;
    if (blockIdx.x == 0 && threadIdx.x < 3) {
        g_lbox[threadIdx.x] = 0.0;
        g_lcls[threadIdx.x] = 0.0;
        g_nb[threadIdx.x] = 0.0;
        g_lobjsum[threadIdx.x] = 0.0;
    }
}

// One block per scale, 512 threads (one per target).
__global__ void target_kernel(const float* __restrict__ p0,
                              const float* __restrict__ p1,
                              const float* __restrict__ p2,
                              const float* __restrict__ targets,
                              const float* __restrict__ anchors,
                              const float* __restrict__ image_size) {
    __shared__ double sh[512];
    int scale = blockIdx.x;
    int tid = threadIdx.x;

    const float* pi;
    int H, W, tobj_off;
    if (scale == 0)      { pi = p0; H = 80; W = 80; tobj_off = TOBJ0; }
    else if (scale == 1) { pi = p1; H = 40; W = 40; tobj_off = TOBJ1; }
    else                 { pi = p2; H = 20; W = 20; tobj_off = TOBJ2; }

    float stride0 = image_size[0] / (float)H;   // for y / h
    float stride1 = image_size[1] / (float)W;   // for x / w

    // anchors for this scale, divided by stride[::-1] = [stride1, stride0]
    float aw[3], ah[3];
#pragma unroll
    for (int a = 0; a < 3; a++) {
        aw[a] = anchors[(scale * 3 + a) * 2 + 0] / stride1;
        ah[a] = anchors[(scale * 3 + a) * 2 + 1] / stride0;
    }

    double lbox = 0.0, lcls = 0.0, nb = 0.0;

    if (tid < NT) {
        const float* tg = targets + tid * 6;
        float t0 = tg[0];
        float t1 = tg[1];
        float gx = tg[2] / stride1;
        float gy = tg[3] / stride0;
        float gw = tg[4] / stride1;
        float gh = tg[5] / stride0;

        // anchor IoU (wh-only), argmax with first-max tie-break
        float best = -1e30f;
        int arg = 0;
#pragma unroll
        for (int a = 0; a < 3; a++) {
            float inter = fminf(aw[a], gw) * fminf(ah[a], gh);
            float uni   = aw[a] * ah[a] + gw * gh - inter;
            float iou   = inter / uni;
            if (iou > best) { best = iou; arg = a; }
        }
        bool mask = best > THRESH;

        if (mask) {
            int b  = (int)t0;
            int c  = (int)t1;
            int gi = (int)gx;
            int gj = (int)gy;
            if (b  < 0) b  = 0; if (b  > BATCH - 1) b  = BATCH - 1;
            if (gi < 0) gi = 0; if (gi > W - 1)     gi = W - 1;
            if (gj < 0) gj = 0; if (gj > H - 1)     gj = H - 1;
            int a_s = arg;

            // tobj scatter-max of 1.0 (racing identical writes is benign)
            g_tobj[tobj_off + ((b * NA + a_s) * H + gj) * W + gi] = 1.0f;

            // gather ps: pi[b, a_s*85 + ch, gj, gi]
            size_t HW = (size_t)H * W;
            const float* base = pi + (((size_t)b * (NA * NCH) + (size_t)a_s * NCH) * HW)
                                   + (size_t)gj * W + gi;

            float ps0 = base[0 * HW];
            float ps1 = base[1 * HW];
            float ps2 = base[2 * HW];
            float ps3 = base[3 * HW];

            float pcx = 1.0f / (1.0f + expf(-ps0));
            float pcy = 1.0f / (1.0f + expf(-ps1));
            float pw  = fminf(expf(ps2), 1000.0f) * aw[a_s];
            float ph  = fminf(expf(ps3), 1000.0f) * ah[a_s];

            float tcx = gx - floorf(gx);
            float tcy = gy - floorf(gy);

            // GIoU
            float px1 = pcx - pw * 0.5f, py1 = pcy - ph * 0.5f;
            float px2 = pcx + pw * 0.5f, py2 = pcy + ph * 0.5f;
            float tx1 = tcx - gw * 0.5f, ty1 = tcy - gh * 0.5f;
            float tx2 = tcx + gw * 0.5f, ty2 = tcy + gh * 0.5f;

            float iw = fmaxf(fminf(px2, tx2) - fmaxf(px1, tx1), 0.0f);
            float ih = fmaxf(fminf(py2, ty2) - fmaxf(py1, ty1), 0.0f);
            float inter = iw * ih;
            float uni   = pw * ph + gw * gh - inter + EPSF;
            float iou   = inter / uni;
            float cw = fmaxf(px2, tx2) - fminf(px1, tx1);
            float ch = fmaxf(py2, ty2) - fminf(py1, ty1);
            float c_area = cw * ch + EPSF;
            float giou = iou - (c_area - uni) / c_area;

            lbox = (double)(1.0f - giou);
            nb   = 1.0;

            // class BCE vs one-hot(c-1)
            float s = 0.0f;
#pragma unroll 4
            for (int j = 0; j < NC; j++) {
                float x = base[(size_t)(5 + j) * HW];
                float t = (j == c - 1) ? 1.0f : 0.0f;
                s += bce_logits(x, t);
            }
            lcls = (double)s;
        }
    }

    double rb = block_reduce_d(lbox, sh);
    double rc = block_reduce_d(lcls, sh);
    double rn = block_reduce_d(nb, sh);
    if (tid == 0) {
        g_lbox[scale] = rb;
        g_lcls[scale] = rc;
        g_nb[scale]   = rn;
    }
}

// BCE(objectness, tobj) summed over B*NA*H*W for one scale.
__global__ void lobj_kernel(const float* __restrict__ pi, int H, int scale, int tobj_off) {
    __shared__ double sh[256];
    int W = H;
    int HW = H * W;
    int n = BATCH * NA * HW;
    int stride = gridDim.x * blockDim.x;
    double local = 0.0;
    for (int i = blockIdx.x * blockDim.x + threadIdx.x; i < n; i += stride) {
        int r  = i % HW;          // y*W + x
        int ba = i / HW;          // b*NA + a
        float logit = pi[((size_t)ba * NCH + 4) * (size_t)HW + r];
        float t = g_tobj[tobj_off + i];
        local += (double)bce_logits(logit, t);
    }
    double blk = block_reduce_d(local, sh);
    if (threadIdx.x == 0) atomicAdd(&g_lobjsum[scale], blk);
}

__global__ void final_kernel(float* __restrict__ out) {
    const double counts[3] = { (double)(BATCH * NA * 80 * 80),
                               (double)(BATCH * NA * 40 * 40),
                               (double)(BATCH * NA * 20 * 20) };
    double lbox = 0.0, lobj = 0.0, lcls = 0.0;
#pragma unroll
    for (int i = 0; i < 3; i++) {
        double nb = g_nb[i] > 1.0 ? g_nb[i] : 1.0;
        lbox += g_lbox[i] / nb;
        lcls += g_lcls[i] / (nb * (double)NC);
        lobj += g_lobjsum[i] / counts[i];
    }
    lbox *= 3.54;
    lobj *= 64.3;
    lcls *= 37.4;
    out[0] = (float)(lbox + lobj + lcls);
    out[1] = (float)lbox;
    out[2] = (float)lobj;
    out[3] = (float)lcls;
}

extern "C" void kernel_launch(void* const* d_in, const int* in_sizes, int n_in,
                              void* d_out, int out_size) {
    const float* p0         = (const float*)d_in[0];
    const float* p1         = (const float*)d_in[1];
    const float* p2         = (const float*)d_in[2];
    const float* targets    = (const float*)d_in[3];
    const float* anchors    = (const float*)d_in[4];
    const float* image_size = (const float*)d_in[5];
    float* out = (float*)d_out;

    zero_kernel<<<512, 256>>>();
    target_kernel<<<3, 512>>>(p0, p1, p2, targets, anchors, image_size);
    lobj_kernel<<<600, 256>>>(p0, 80, 0, TOBJ0);
    lobj_kernel<<<300, 256>>>(p1, 40, 1, TOBJ1);
    lobj_kernel<<<75,  256>>>(p2, 20, 2, TOBJ2);
    final_kernel<<<1, 1>>>(out);
}

// round 2
// speedup vs baseline: 1.4878x; 1.4878x over previous
#include <cuda_runtime.h>
#include <math.h>

#define BATCH 16
#define NA 3
#define NC 80
#define NCH 85            // 5 + NC
#define NT 512            // B*M targets
#define THRESH 0.6f
#define EPSF 1e-7f

#define N0 307200         // 16*3*80*80
#define N1 76800          // 16*3*40*40
#define N2 19200          // 16*3*20*20

#define NBLK 148
#define NTHR 512

__device__ double g_lbox[3];
__device__ double g_lcls[3];
__device__ double g_nb[3];
__device__ double g_corr[3];   // sum of -logit over unique masked cells
__device__ double g_base[3];   // sum of bce(logit, 0) over all cells
__device__ int    g_done = 0;

__device__ __forceinline__ float softplusf(float x) {
    // bce(x, 0) = max(x,0) + log1p(exp(-|x|)) = softplus(x)
    return fmaxf(x, 0.0f) + log1pf(expf(-fabsf(x)));
}

__device__ double blk_reduce(double v, double* sh) {
    int t = threadIdx.x;
    sh[t] = v;
    __syncthreads();
#pragma unroll
    for (int s = NTHR / 2; s > 0; s >>= 1) {
        if (t < s) sh[t] += sh[t + s];
        __syncthreads();
    }
    double r = sh[0];
    __syncthreads();
    return r;
}

__global__ void __launch_bounds__(NTHR)
yolo_fused(const float* __restrict__ p0,
           const float* __restrict__ p1,
           const float* __restrict__ p2,
           const float* __restrict__ targets,
           const float* __restrict__ anchors,
           const float* __restrict__ image_size,
           float* __restrict__ out)
{
    __shared__ double   sh[NTHR];
    __shared__ int      table[1024];
    __shared__ unsigned s_off[NT];
    __shared__ int      s_cls[NT];
    __shared__ int      s_cnt;

    int tid = threadIdx.x;
    int blk = blockIdx.x;

    if (blk < 3) {
        // ---------------- target block for scale `blk` ----------------
        const float* pi;
        int H, W;
        if (blk == 0)      { pi = p0; H = 80; W = 80; }
        else if (blk == 1) { pi = p1; H = 40; W = 40; }
        else               { pi = p2; H = 20; W = 20; }
        int HW = H * W;

        float stride0 = image_size[0] / (float)H;   // y / h
        float stride1 = image_size[1] / (float)W;   // x / w

        float aw[3], ah[3];
#pragma unroll
        for (int a = 0; a < 3; a++) {
            aw[a] = anchors[(blk * 3 + a) * 2 + 0] / stride1;
            ah[a] = anchors[(blk * 3 + a) * 2 + 1] / stride0;
        }

        table[tid] = -1;
        table[tid + 512] = -1;
        if (tid == 0) s_cnt = 0;
        __syncthreads();

        double lbox = 0.0, nb = 0.0, corr = 0.0;

        {
            const float* tg = targets + tid * 6;
            float t0 = tg[0];
            float t1 = tg[1];
            float gx = tg[2] / stride1;
            float gy = tg[3] / stride0;
            float gw = tg[4] / stride1;
            float gh = tg[5] / stride0;

            float best = -1e30f;
            int arg = 0;
#pragma unroll
            for (int a = 0; a < 3; a++) {
                float inter = fminf(aw[a], gw) * fminf(ah[a], gh);
                float uni   = aw[a] * ah[a] + gw * gh - inter;
                float iou   = inter / uni;
                if (iou > best) { best = iou; arg = a; }
            }

            if (best > THRESH) {
                int b  = (int)t0;
                int c  = (int)t1;
                int gi = (int)gx;
                int gj = (int)gy;
                if (b  < 0) b  = 0; if (b  > BATCH - 1) b  = BATCH - 1;
                if (gi < 0) gi = 0; if (gi > W - 1)     gi = W - 1;
                if (gj < 0) gj = 0; if (gj > H - 1)     gj = H - 1;
                int a_s = arg;

                int cell = ((b * NA + a_s) * H + gj) * W + gi;
                unsigned off = (unsigned)((b * NA + a_s) * NCH) * (unsigned)HW
                             + (unsigned)(gj * W + gi);

                float ps0 = pi[off];
                float ps1 = pi[off + HW];
                float ps2 = pi[off + 2 * HW];
                float ps3 = pi[off + 3 * HW];
                float lg  = pi[off + 4 * HW];   // objectness logit

                float pcx = 1.0f / (1.0f + expf(-ps0));
                float pcy = 1.0f / (1.0f + expf(-ps1));
                float pw  = fminf(expf(ps2), 1000.0f) * aw[a_s];
                float ph  = fminf(expf(ps3), 1000.0f) * ah[a_s];

                float tcx = gx - floorf(gx);
                float tcy = gy - floorf(gy);

                float px1 = pcx - pw * 0.5f, py1 = pcy - ph * 0.5f;
                float px2 = pcx + pw * 0.5f, py2 = pcy + ph * 0.5f;
                float tx1 = tcx - gw * 0.5f, ty1 = tcy - gh * 0.5f;
                float tx2 = tcx + gw * 0.5f, ty2 = tcy + gh * 0.5f;

                float iw = fmaxf(fminf(px2, tx2) - fmaxf(px1, tx1), 0.0f);
                float ih = fmaxf(fminf(py2, ty2) - fmaxf(py1, ty1), 0.0f);
                float inter = iw * ih;
                float uni   = pw * ph + gw * gh - inter + EPSF;
                float iou   = inter / uni;
                float cw = fmaxf(px2, tx2) - fminf(px1, tx1);
                float ch = fmaxf(py2, ty2) - fminf(py1, ty1);
                float c_area = cw * ch + EPSF;
                float giou = iou - (c_area - uni) / c_area;

                lbox = (double)(1.0f - giou);
                nb   = 1.0;

                // dedup scatter: owner of first CAS applies the tobj correction
                unsigned h = ((unsigned)cell * 2654435761u) & 1023u;
                bool owner = false;
                while (true) {
                    int prev = atomicCAS(&table[h], -1, cell);
                    if (prev == -1)   { owner = true; break; }
                    if (prev == cell) { break; }
                    h = (h + 1) & 1023u;
                }
                if (owner) corr = -(double)lg;

                int slot = atomicAdd(&s_cnt, 1);
                s_off[slot] = off;
                s_cls[slot] = c - 1;
            }
        }
        __syncthreads();

        // cooperative class-BCE over (masked targets x 80 classes)
        int cnt = s_cnt;
        double lcls = 0.0;
        for (int k = tid; k < cnt * NC; k += NTHR) {
            int idx = k / NC;
            int j   = k - idx * NC;
            float x = pi[s_off[idx] + (unsigned)(5 + j) * (unsigned)HW];
            float sp = softplusf(x);               // bce(x,0)
            lcls += (double)(sp - ((j == s_cls[idx]) ? x : 0.0f));
        }

        double rb = blk_reduce(lbox, sh);
        double rn = blk_reduce(nb,   sh);
        double rc = blk_reduce(corr, sh);
        double rl = blk_reduce(lcls, sh);
        if (tid == 0) {
            g_lbox[blk] = rb;
            g_nb[blk]   = rn;
            g_corr[blk] = rc;
            g_lcls[blk] = rl;
        }
    } else {
        // ---------------- objectness base BCE (t = 0 everywhere) ----------------
        long gid    = (long)(blk - 3) * NTHR + tid;
        long stride = (long)(NBLK - 3) * NTHR;

        double l0 = 0.0, l1 = 0.0, l2 = 0.0;
        for (long i = gid; i < N0; i += stride) {
            int ba = (int)(i / 6400);
            int r  = (int)(i - (long)ba * 6400);
            l0 += (double)softplusf(p0[((size_t)ba * NCH + 4) * 6400 + r]);
        }
        for (long i = gid; i < N1; i += stride) {
            int ba = (int)(i / 1600);
            int r  = (int)(i - (long)ba * 1600);
            l1 += (double)softplusf(p1[((size_t)ba * NCH + 4) * 1600 + r]);
        }
        for (long i = gid; i < N2; i += stride) {
            int ba = (int)(i / 400);
            int r  = (int)(i - (long)ba * 400);
            l2 += (double)softplusf(p2[((size_t)ba * NCH + 4) * 400 + r]);
        }

        double r0 = blk_reduce(l0, sh);
        double r1 = blk_reduce(l1, sh);
        double r2 = blk_reduce(l2, sh);
        if (tid == 0) {
            atomicAdd(&g_base[0], r0);
            atomicAdd(&g_base[1], r1);
            atomicAdd(&g_base[2], r2);
        }
    }

    // ---------------- finisher: last block combines + resets state ----------------
    __syncthreads();
    __threadfence();
    if (tid == 0) {
        int old = atomicAdd(&g_done, 1);
        if (old == NBLK - 1) {
            const double counts[3] = { (double)N0, (double)N1, (double)N2 };
            double lbox = 0.0, lobj = 0.0, lcls = 0.0;
#pragma unroll
            for (int i = 0; i < 3; i++) {
                double nbv = g_nb[i] > 1.0 ? g_nb[i] : 1.0;
                lbox += g_lbox[i] / nbv;
                lcls += g_lcls[i] / (nbv * (double)NC);
                lobj += (g_base[i] + g_corr[i]) / counts[i];
            }
            lbox *= 3.54;
            lobj *= 64.3;
            lcls *= 37.4;
            out[0] = (float)(lbox + lobj + lcls);
            out[1] = (float)lbox;
            out[2] = (float)lobj;
            out[3] = (float)lcls;
#pragma unroll
            for (int i = 0; i < 3; i++) {
                g_lbox[i] = 0.0; g_lcls[i] = 0.0; g_nb[i] = 0.0;
                g_corr[i] = 0.0; g_base[i] = 0.0;
            }
            g_done = 0;
            __threadfence();
        }
    }
}

extern "C" void kernel_launch(void* const* d_in, const int* in_sizes, int n_in,
                              void* d_out, int out_size) {
    const float* p0         = (const float*)d_in[0];
    const float* p1         = (const float*)d_in[1];
    const float* p2         = (const float*)d_in[2];
    const float* targets    = (const float*)d_in[3];
    const float* anchors    = (const float*)d_in[4];
    const float* image_size = (const float*)d_in[5];
    float* out = (float*)d_out;

    yolo_fused<<<NBLK, NTHR>>>(p0, p1, p2, targets, anchors, image_size, out);
}

// round 3
// speedup vs baseline: 1.6486x; 1.1081x over previous
#include <cuda_runtime.h>
#include <math.h>

#define BATCH 16
#define NA 3
#define NC 80
#define NCH 85
#define NT 512
#define THRESH 0.6f
#define EPSF 1e-7f

#define N0 307200
#define N1 76800
#define N2 19200

#define NBLK 148
#define NTHR 512
#define OBJ_BLKS (NBLK - 3)
#define GSTRIDE (OBJ_BLKS * NTHR)   // 74240

// float4 counts per (b,a) plane
#define PL0 1600   // 6400/4
#define PL1 400
#define PL2 100
#define T0 76800   // 48*1600
#define T1 19200
#define T2 4800

__device__ double g_lbox[3];
__device__ double g_lcls[3];
__device__ double g_nb[3];
__device__ double g_corr[3];
__device__ double g_base[3];
__device__ unsigned g_done = 0;

__device__ __forceinline__ float softplus_fast(float x) {
    // bce(x,0) = max(x,0) + log1p(exp(-|x|))
    return fmaxf(x, 0.0f) + __logf(1.0f + __expf(-fabsf(x)));
}

__device__ __forceinline__ double warp_red(double v) {
#pragma unroll
    for (int o = 16; o > 0; o >>= 1)
        v += __shfl_down_sync(0xffffffffu, v, o);
    return v;
}

__global__ void __launch_bounds__(NTHR)
yolo_fused(const float* __restrict__ p0,
           const float* __restrict__ p1,
           const float* __restrict__ p2,
           const float* __restrict__ targets,
           const float* __restrict__ anchors,
           const float* __restrict__ image_size,
           float* __restrict__ out)
{
    __shared__ double sred[16][4];

    int tid  = threadIdx.x;
    int blk  = blockIdx.x;
    int lane = tid & 31;
    int wid  = tid >> 5;

    if (blk >= 3) {
        // ---------- objectness base BCE: all loads issued up-front ----------
        int gid = (blk - 3) * NTHR + tid;

        const float4* p0v = reinterpret_cast<const float4*>(p0);
        const float4* p1v = reinterpret_cast<const float4*>(p1);
        const float4* p2v = reinterpret_cast<const float4*>(p2);

        int i0a = gid;                 // always < T0
        int i0b = gid + GSTRIDE;       // < T0 only for gid < 2560
        bool h0b = i0b < T0;
        bool h1  = gid < T1;
        bool h2  = gid < T2;

        int ba0a = i0a / PL0;
        int ba0b = i0b / PL0;
        int ba1  = gid / PL1;
        int ba2  = gid / PL2;

        float4 va = p0v[(size_t)(ba0a * NCH + 4) * PL0 + (i0a - ba0a * PL0)];
        float4 vb = h0b ? p0v[(size_t)(ba0b * NCH + 4) * PL0 + (i0b - ba0b * PL0)]
                        : make_float4(0.f, 0.f, 0.f, 0.f);
        float4 vc = h1  ? p1v[(size_t)(ba1 * NCH + 4) * PL1 + (gid - ba1 * PL1)]
                        : make_float4(0.f, 0.f, 0.f, 0.f);
        float4 vd = h2  ? p2v[(size_t)(ba2 * NCH + 4) * PL2 + (gid - ba2 * PL2)]
                        : make_float4(0.f, 0.f, 0.f, 0.f);

        double l0 = (double)(softplus_fast(va.x) + softplus_fast(va.y) +
                             softplus_fast(va.z) + softplus_fast(va.w));
        if (h0b) l0 += (double)(softplus_fast(vb.x) + softplus_fast(vb.y) +
                                softplus_fast(vb.z) + softplus_fast(vb.w));
        double l1 = h1 ? (double)(softplus_fast(vc.x) + softplus_fast(vc.y) +
                                  softplus_fast(vc.z) + softplus_fast(vc.w)) : 0.0;
        double l2 = h2 ? (double)(softplus_fast(vd.x) + softplus_fast(vd.y) +
                                  softplus_fast(vd.z) + softplus_fast(vd.w)) : 0.0;

        l0 = warp_red(l0);
        l1 = warp_red(l1);
        l2 = warp_red(l2);
        if (lane == 0) { sred[wid][0] = l0; sred[wid][1] = l1; sred[wid][2] = l2; sred[wid][3] = 0.0; }
        __syncthreads();
        if (wid < 3) {
            double a = (lane < 16) ? sred[lane][wid] : 0.0;
            a = warp_red(a);
            if (lane == 0) sred[0][wid] = a;   // stash channel result
        }
        __syncthreads();
        if (tid == 0) {
            atomicAdd(&g_base[0], sred[0][0]);
            atomicAdd(&g_base[1], sred[0][1]);
            atomicAdd(&g_base[2], sred[0][2]);
        }
    } else {
        // ---------- target block for scale `blk` ----------
        __shared__ int      table[1024];
        __shared__ unsigned s_off[NT];
        __shared__ int      s_cls[NT];
        __shared__ int      s_cnt;

        const float* pi;
        int H, W;
        if (blk == 0)      { pi = p0; H = 80; W = 80; }
        else if (blk == 1) { pi = p1; H = 40; W = 40; }
        else               { pi = p2; H = 20; W = 20; }
        int HW = H * W;

        float stride0 = image_size[0] / (float)H;
        float stride1 = image_size[1] / (float)W;

        float aw[3], ah[3];
#pragma unroll
        for (int a = 0; a < 3; a++) {
            aw[a] = anchors[(blk * 3 + a) * 2 + 0] / stride1;
            ah[a] = anchors[(blk * 3 + a) * 2 + 1] / stride0;
        }

        table[tid] = -1;
        table[tid + 512] = -1;
        if (tid == 0) s_cnt = 0;
        __syncthreads();

        double lbox = 0.0, nb = 0.0, corr = 0.0;

        {
            const float* tg = targets + tid * 6;
            float t0 = tg[0];
            float t1 = tg[1];
            float gx = tg[2] / stride1;
            float gy = tg[3] / stride0;
            float gw = tg[4] / stride1;
            float gh = tg[5] / stride0;

            float best = -1e30f;
            int arg = 0;
#pragma unroll
            for (int a = 0; a < 3; a++) {
                float inter = fminf(aw[a], gw) * fminf(ah[a], gh);
                float uni   = aw[a] * ah[a] + gw * gh - inter;
                float iou   = inter / uni;
                if (iou > best) { best = iou; arg = a; }
            }

            if (best > THRESH) {
                int b  = (int)t0;
                int c  = (int)t1;
                int gi = (int)gx;
                int gj = (int)gy;
                if (b  < 0) b  = 0; if (b  > BATCH - 1) b  = BATCH - 1;
                if (gi < 0) gi = 0; if (gi > W - 1)     gi = W - 1;
                if (gj < 0) gj = 0; if (gj > H - 1)     gj = H - 1;
                int a_s = arg;

                int cell = ((b * NA + a_s) * H + gj) * W + gi;
                unsigned off = (unsigned)((b * NA + a_s) * NCH) * (unsigned)HW
                             + (unsigned)(gj * W + gi);

                float ps0 = pi[off];
                float ps1 = pi[off + HW];
                float ps2 = pi[off + 2 * HW];
                float ps3 = pi[off + 3 * HW];
                float lg  = pi[off + 4 * HW];

                float pcx = 1.0f / (1.0f + __expf(-ps0));
                float pcy = 1.0f / (1.0f + __expf(-ps1));
                float pw  = fminf(__expf(ps2), 1000.0f) * aw[a_s];
                float ph  = fminf(__expf(ps3), 1000.0f) * ah[a_s];

                float tcx = gx - floorf(gx);
                float tcy = gy - floorf(gy);

                float px1 = pcx - pw * 0.5f, py1 = pcy - ph * 0.5f;
                float px2 = pcx + pw * 0.5f, py2 = pcy + ph * 0.5f;
                float tx1 = tcx - gw * 0.5f, ty1 = tcy - gh * 0.5f;
                float tx2 = tcx + gw * 0.5f, ty2 = tcy + gh * 0.5f;

                float iw = fmaxf(fminf(px2, tx2) - fmaxf(px1, tx1), 0.0f);
                float ih = fmaxf(fminf(py2, ty2) - fmaxf(py1, ty1), 0.0f);
                float inter = iw * ih;
                float uni   = pw * ph + gw * gh - inter + EPSF;
                float iou   = inter / uni;
                float cw = fmaxf(px2, tx2) - fminf(px1, tx1);
                float ch = fmaxf(py2, ty2) - fminf(py1, ty1);
                float c_area = cw * ch + EPSF;
                float giou = iou - (c_area - uni) / c_area;

                lbox = (double)(1.0f - giou);
                nb   = 1.0;

                unsigned h = ((unsigned)cell * 2654435761u) & 1023u;
                bool owner = false;
                while (true) {
                    int prev = atomicCAS(&table[h], -1, cell);
                    if (prev == -1)   { owner = true; break; }
                    if (prev == cell) { break; }
                    h = (h + 1) & 1023u;
                }
                if (owner) corr = -(double)lg;

                int slot = atomicAdd(&s_cnt, 1);
                s_off[slot] = off;
                s_cls[slot] = c - 1;
            }
        }
        __syncthreads();

        int cnt = s_cnt;
        double lcls = 0.0;
        for (int k = tid; k < cnt * NC; k += NTHR) {
            int idx = k / NC;
            int j   = k - idx * NC;
            float x = pi[s_off[idx] + (unsigned)(5 + j) * (unsigned)HW];
            float sp = softplus_fast(x);
            lcls += (double)(sp - ((j == s_cls[idx]) ? x : 0.0f));
        }

        lbox = warp_red(lbox);
        nb   = warp_red(nb);
        corr = warp_red(corr);
        lcls = warp_red(lcls);
        if (lane == 0) {
            sred[wid][0] = lbox; sred[wid][1] = nb;
            sred[wid][2] = corr; sred[wid][3] = lcls;
        }
        __syncthreads();
        if (wid < 4) {
            double a = (lane < 16) ? sred[lane][wid] : 0.0;
            a = warp_red(a);
            if (lane == 0) sred[0][wid] = a;
        }
        __syncthreads();
        if (tid == 0) {
            g_lbox[blk] = sred[0][0];
            g_nb[blk]   = sred[0][1];
            g_corr[blk] = sred[0][2];
            g_lcls[blk] = sred[0][3];
        }
    }

    // ---------- finisher: tid 0 only ----------
    __syncthreads();
    if (tid == 0) {
        __threadfence();
        unsigned old = atomicAdd(&g_done, 1u);
        if (old == NBLK - 1) {
            __threadfence();
            const double counts[3] = { (double)N0, (double)N1, (double)N2 };
            double lbox = 0.0, lobj = 0.0, lcls = 0.0;
#pragma unroll
            for (int i = 0; i < 3; i++) {
                double nbv = g_nb[i] > 1.0 ? g_nb[i] : 1.0;
                lbox += g_lbox[i] / nbv;
                lcls += g_lcls[i] / (nbv * (double)NC);
                lobj += (g_base[i] + g_corr[i]) / counts[i];
            }
            lbox *= 3.54;
            lobj *= 64.3;
            lcls *= 37.4;
            out[0] = (float)(lbox + lobj + lcls);
            out[1] = (float)lbox;
            out[2] = (float)lobj;
            out[3] = (float)lcls;
#pragma unroll
            for (int i = 0; i < 3; i++) {
                g_lbox[i] = 0.0; g_lcls[i] = 0.0; g_nb[i] = 0.0;
                g_corr[i] = 0.0; g_base[i] = 0.0;
            }
            g_done = 0u;
            __threadfence();
        }
    }
}

extern "C" void kernel_launch(void* const* d_in, const int* in_sizes, int n_in,
                              void* d_out, int out_size) {
    const float* p0         = (const float*)d_in[0];
    const float* p1         = (const float*)d_in[1];
    const float* p2         = (const float*)d_in[2];
    const float* targets    = (const float*)d_in[3];
    const float* anchors    = (const float*)d_in[4];
    const float* image_size = (const float*)d_in[5];
    float* out = (float*)d_out;

    yolo_fused<<<NBLK, NTHR>>>(p0, p1, p2, targets, anchors, image_size, out);
}